// round 7
// baseline (speedup 1.0000x reference)
#include <cuda_runtime.h>

#define THREADS 128
#define NBLOCKS 888   // 148 SMs x 6 CTAs -> persistent grid

struct Idx6 { int h, t, r, nh, nt, nr; };

__device__ __forceinline__ void load_idx(
    Idx6& x,
    const int* __restrict__ ph, const int* __restrict__ pt, const int* __restrict__ pr,
    const int* __restrict__ nh, const int* __restrict__ nt, const int* __restrict__ nr,
    int i)
{
    x.h  = __ldg(ph + i);
    x.t  = __ldg(pt + i);
    x.r  = __ldg(pr + i);
    x.nh = __ldg(nh + i);
    x.nt = __ldg(nt + i);
    x.nr = __ldg(nr + i);
}

struct Pay { float4 v, h, t, r, nh, nt, nr; };

__device__ __forceinline__ void gather(
    Pay& P, const Idx6& x,
    const float4* __restrict__ ent, const float4* __restrict__ vvrel,
    const float4* __restrict__ bases, int lane)
{
    P.v  = __ldg(bases + (size_t)x.r  * 32 + lane);
    P.h  = __ldg(ent   + (size_t)x.h  * 32 + lane);
    P.t  = __ldg(ent   + (size_t)x.t  * 32 + lane);
    P.r  = __ldg(vvrel + (size_t)x.r  * 32 + lane);
    P.nh = __ldg(ent   + (size_t)x.nh * 32 + lane);
    P.nt = __ldg(ent   + (size_t)x.nt * 32 + lane);
    P.nr = __ldg(vvrel + (size_t)x.nr * 32 + lane);
}

// Projection linearity with shared v: sum|P(h)+P(r)-P(t)| = sum|P(h+r-t)|.
__device__ __forceinline__ void compute_store(
    const Pay& P, float* __restrict__ out, int i, int n, int lane)
{
    float4 dp, dn;
    dp.x = P.h.x + P.r.x - P.t.x;      dp.y = P.h.y + P.r.y - P.t.y;
    dp.z = P.h.z + P.r.z - P.t.z;      dp.w = P.h.w + P.r.w - P.t.w;
    dn.x = P.nh.x + P.nr.x - P.nt.x;   dn.y = P.nh.y + P.nr.y - P.nt.y;
    dn.z = P.nh.z + P.nr.z - P.nt.z;   dn.w = P.nh.w + P.nr.w - P.nt.w;

    const float4 v = P.v;
    float pvv = v.x * v.x  + v.y * v.y  + v.z * v.z  + v.w * v.w;
    float pvp = v.x * dp.x + v.y * dp.y + v.z * dp.z + v.w * dp.w;
    float pvn = v.x * dn.x + v.y * dn.y + v.z * dn.z + v.w * dn.w;
    #pragma unroll
    for (int o = 16; o > 0; o >>= 1) {
        pvv += __shfl_xor_sync(0xFFFFFFFFu, pvv, o);
        pvp += __shfl_xor_sync(0xFFFFFFFFu, pvp, o);
        pvn += __shfl_xor_sync(0xFFFFFFFFu, pvn, o);
    }
    const float inv_vv = 1.0f / pvv;
    const float cp = pvp * inv_vv;
    const float cn = pvn * inv_vv;

    float sp = fabsf(dp.x - cp * v.x) + fabsf(dp.y - cp * v.y)
             + fabsf(dp.z - cp * v.z) + fabsf(dp.w - cp * v.w);
    float sn = fabsf(dn.x - cn * v.x) + fabsf(dn.y - cn * v.y)
             + fabsf(dn.z - cn * v.z) + fabsf(dn.w - cn * v.w);
    #pragma unroll
    for (int o = 16; o > 0; o >>= 1) {
        sp += __shfl_xor_sync(0xFFFFFFFFu, sp, o);
        sn += __shfl_xor_sync(0xFFFFFFFFu, sn, o);
    }

    if (lane == 0) {
        out[i]     = sp;
        out[n + i] = sn;
    }
}

__global__ __launch_bounds__(THREADS, 6)
void transh_score_dbuf_kernel(
    const int* __restrict__ pos_h, const int* __restrict__ pos_t, const int* __restrict__ pos_r,
    const int* __restrict__ neg_h, const int* __restrict__ neg_t, const int* __restrict__ neg_r,
    const float4* __restrict__ ent, const float4* __restrict__ vvrel,
    const float4* __restrict__ bases,
    float* __restrict__ out, int n)
{
    const int lane   = threadIdx.x & 31;
    const int stride = (gridDim.x * blockDim.x) >> 5;
    const int w      = (blockIdx.x * blockDim.x + threadIdx.x) >> 5;
    if (w >= n) return;

    // Pipeline state. iA/iB are the triples whose payloads are (being) loaded
    // into A/B. Indices for the triple after the most recent gather are always
    // in flight before compute starts.
    int iA = w;
    Idx6 xa; load_idx(xa, pos_h, pos_t, pos_r, neg_h, neg_t, neg_r, iA);
    Pay A;  gather(A, xa, ent, vvrel, bases, lane);

    int iB = iA + stride;
    bool hasB = (iB < n);
    Idx6 xb; load_idx(xb, pos_h, pos_t, pos_r, neg_h, neg_t, neg_r, hasB ? iB : iA);

    for (;;) {
        // --- Compute A; B's payloads + the following indices go in flight first ---
        Pay B;
        if (hasB) gather(B, xb, ent, vvrel, bases, lane);
        int iC = iB + stride;
        bool hasC = hasB && (iC < n);
        load_idx(xa, pos_h, pos_t, pos_r, neg_h, neg_t, neg_r, hasC ? iC : iA);
        compute_store(A, out, iA, n, lane);
        if (!hasB) return;

        // --- Compute B; A's (=iC) payloads + following indices in flight first ---
        if (hasC) gather(A, xa, ent, vvrel, bases, lane);
        int iD = iC + stride;
        bool hasD = hasC && (iD < n);
        load_idx(xb, pos_h, pos_t, pos_r, neg_h, neg_t, neg_r, hasD ? iD : iB);
        compute_store(B, out, iB, n, lane);
        if (!hasC) return;

        iA = iC; iB = iD; hasB = hasD;
    }
}

extern "C" void kernel_launch(void* const* d_in, const int* in_sizes, int n_in,
                              void* d_out, int out_size)
{
    const int*    pos_h = (const int*)d_in[0];
    const int*    pos_t = (const int*)d_in[1];
    const int*    pos_r = (const int*)d_in[2];
    const int*    neg_h = (const int*)d_in[3];
    const int*    neg_t = (const int*)d_in[4];
    const int*    neg_r = (const int*)d_in[5];
    const float4* ent   = (const float4*)d_in[6];
    const float4* vvrel = (const float4*)d_in[7];
    const float4* bases = (const float4*)d_in[8];
    float* out = (float*)d_out;

    const int n = in_sizes[0];  // 65536 triples
    transh_score_dbuf_kernel<<<NBLOCKS, THREADS>>>(
        pos_h, pos_t, pos_r, neg_h, neg_t, neg_r, ent, vvrel, bases, out, n);
}